// round 3
// baseline (speedup 1.0000x reference)
#include <cuda_runtime.h>
#include <cuda_bf16.h>

// Problem constants
#define B_SZ   512
#define IN_F   512
#define OUT_F  64
#define KD     16
#define NF     (OUT_F * KD)   // 1024

typedef unsigned long long u64;

// Scratch for M laid out [o][b][k]  (64 * 512 * 16 floats = 2 MB)
__device__ float g_M[OUT_F * B_SZ * KD];

// ---- packed f32x2 helpers (sm_103a) ---------------------------------------
__device__ __forceinline__ u64 fadd2(u64 a, u64 b) {
    u64 r; asm("add.rn.f32x2 %0, %1, %2;" : "=l"(r) : "l"(a), "l"(b)); return r;
}
__device__ __forceinline__ u64 ffma2(u64 a, u64 b, u64 c) {
    u64 r; asm("fma.rn.f32x2 %0, %1, %2, %3;" : "=l"(r) : "l"(a), "l"(b), "l"(c)); return r;
}
__device__ __forceinline__ u64 fabs2(u64 a) {
    return a & 0x7FFFFFFF7FFFFFFFULL;            // sign clear -> alu pipe
}
__device__ __forceinline__ u64 pack2(float lo, float hi) {
    u64 r; asm("mov.b64 %0, {%1, %2};" : "=l"(r) : "f"(lo), "f"(hi)); return r;
}
__device__ __forceinline__ void unpack2(u64 v, float& lo, float& hi) {
    asm("mov.b64 {%0, %1}, %2;" : "=f"(lo), "=f"(hi) : "l"(v));
}

// ---------------------------------------------------------------------------
// Kernel A: M = x[512,512] @ T[512,1024], stored transposed to [o][b][k]
// Tile 32(M) x 64(N), K-chunk 32, 256 threads, 2x4 microtile, packed FFMA2.
// A staged duplicated as (a,a) float2 so the inner loop has no pack ops.
// Grid = 256 blocks -> every SM busy, all resident.
// ---------------------------------------------------------------------------
#define TM 32
#define TN 64
#define TK 32

__global__ __launch_bounds__(256) void mbd_gemm_kernel(
    const float* __restrict__ x, const float* __restrict__ T)
{
    __shared__ float2 xsd[TM][TK];     // duplicated A: (a,a)  8 KB
    __shared__ float  Ts[TK][TN];      // [k][n]               8 KB

    const int tid = threadIdx.x;
    const int tx = tid & 15;           // n microtile (4 cols)
    const int ty = tid >> 4;           // m microtile (2 rows)
    const int m0 = blockIdx.y * TM;
    const int n0 = blockIdx.x * TN;
    const int r = ty * 2;
    const int c = tx * 4;

    u64 acc[2][2];
    acc[0][0] = acc[0][1] = acc[1][0] = acc[1][1] = 0ULL;

    for (int k0 = 0; k0 < IN_F; k0 += TK) {
        // Load A tile 32x32 (1024 floats): one float4/thread, store duplicated
        {
            int idx = tid * 4;
            int m = idx >> 5;              // idx / 32
            int k = idx & 31;
            float4 v = *(const float4*)&x[(m0 + m) * IN_F + k0 + k];
            xsd[m][k + 0] = make_float2(v.x, v.x);
            xsd[m][k + 1] = make_float2(v.y, v.y);
            xsd[m][k + 2] = make_float2(v.z, v.z);
            xsd[m][k + 3] = make_float2(v.w, v.w);
        }
        // Load B tile 32x64 (2048 floats): two float4/thread
        {
#pragma unroll
            for (int t = 0; t < 2; t++) {
                int idx = tid * 4 + t * 1024;
                int k = idx >> 6;
                int n = idx & 63;
                float4 v = *(const float4*)&T[(k0 + k) * NF + n0 + n];
                *(float4*)&Ts[k][n] = v;
            }
        }
        __syncthreads();

#pragma unroll
        for (int kk = 0; kk < TK; kk++) {
            u64 a0 = *(const u64*)&xsd[r + 0][kk];
            u64 a1 = *(const u64*)&xsd[r + 1][kk];
            ulonglong2 bb = *(const ulonglong2*)&Ts[kk][c];
            acc[0][0] = ffma2(a0, bb.x, acc[0][0]);
            acc[0][1] = ffma2(a0, bb.y, acc[0][1]);
            acc[1][0] = ffma2(a1, bb.x, acc[1][0]);
            acc[1][1] = ffma2(a1, bb.y, acc[1][1]);
        }
        __syncthreads();
    }

    // Epilogue: g_M[o][b][k]. c is a multiple of 4 -> 4 cols inside one o.
    const int of = n0 + c;
    const int o  = of >> 4;
    const int k  = of & 15;
#pragma unroll
    for (int ii = 0; ii < 2; ii++) {
        int b = m0 + r + ii;
        ulonglong2 v; v.x = acc[ii][0]; v.y = acc[ii][1];
        *(ulonglong2*)&g_M[(o * B_SZ + b) * KD + k] = v;
    }
}

// ---------------------------------------------------------------------------
// Kernel B: per feature o, S[j] = sum_i exp(-sum_k |M[j,k]-M[i,k]|)
// out[j,o] = w[j] * (S[j] - 1)
// grid (64 o, 8 j-chunks), 128 threads = 32 j-pairs x 4 i-quarters.
// Each thread owns TWO adjacent j (halves LDS per pair, doubles ILP).
// ---------------------------------------------------------------------------
__global__ __launch_bounds__(128) void mbd_pairwise_kernel(
    const float* __restrict__ w, float* __restrict__ out)
{
    __shared__ float sM[B_SZ * KD];            // 32 KB
    __shared__ float red[4][32][2];            // [q][jj][which-j]

    const int o   = blockIdx.x;
    const int tid = threadIdx.x;
    const int jj  = tid & 31;                  // j-pair index in chunk
    const int q   = tid >> 5;                  // i-quarter 0..3
    const int j0  = blockIdx.y * 64 + jj * 2;  // first of the two j's

    // Stage M_o (contiguous 32 KB), float4 coalesced
    {
        const float4* src = (const float4*)(g_M + o * (B_SZ * KD));
        float4* dst = (float4*)sM;
#pragma unroll
        for (int t = 0; t < 16; t++)
            dst[tid + t * 128] = src[tid + t * 128];
    }
    __syncthreads();

    // Pre-negated packed rows for both j's
    u64 mA[8], mB[8];
#pragma unroll
    for (int p = 0; p < 8; p++) {
        mA[p] = pack2(-sM[j0 * KD + 2 * p],       -sM[j0 * KD + 2 * p + 1]);
        mB[p] = pack2(-sM[(j0 + 1) * KD + 2 * p], -sM[(j0 + 1) * KD + 2 * p + 1]);
    }

    const ulonglong2* s2 = (const ulonglong2*)sM;
    float S0 = 0.f, S1 = 0.f;
    const int i0 = q * 128;

#pragma unroll 2
    for (int i = i0; i < i0 + 128; i++) {
        ulonglong2 v0 = s2[i * 4 + 0];         // warp-uniform -> broadcast
        ulonglong2 v1 = s2[i * 4 + 1];
        ulonglong2 v2 = s2[i * 4 + 2];
        ulonglong2 v3 = s2[i * 4 + 3];

        u64 a0 = fabs2(fadd2(v0.x, mA[0]));
        u64 a1 = fabs2(fadd2(v0.y, mA[1]));
        u64 a2 = fabs2(fadd2(v1.x, mA[2]));
        u64 a3 = fabs2(fadd2(v1.y, mA[3]));
        u64 a4 = fabs2(fadd2(v2.x, mA[4]));
        u64 a5 = fabs2(fadd2(v2.y, mA[5]));
        u64 a6 = fabs2(fadd2(v3.x, mA[6]));
        u64 a7 = fabs2(fadd2(v3.y, mA[7]));
        u64 tA = fadd2(fadd2(fadd2(a0, a1), fadd2(a2, a3)),
                       fadd2(fadd2(a4, a5), fadd2(a6, a7)));

        u64 b0 = fabs2(fadd2(v0.x, mB[0]));
        u64 b1 = fabs2(fadd2(v0.y, mB[1]));
        u64 b2 = fabs2(fadd2(v1.x, mB[2]));
        u64 b3 = fabs2(fadd2(v1.y, mB[3]));
        u64 b4 = fabs2(fadd2(v2.x, mB[4]));
        u64 b5 = fabs2(fadd2(v2.y, mB[5]));
        u64 b6 = fabs2(fadd2(v3.x, mB[6]));
        u64 b7 = fabs2(fadd2(v3.y, mB[7]));
        u64 tB = fadd2(fadd2(fadd2(b0, b1), fadd2(b2, b3)),
                       fadd2(fadd2(b4, b5), fadd2(b6, b7)));

        float la, ha, lb, hb;
        unpack2(tA, la, ha);
        unpack2(tB, lb, hb);
        S0 += __expf(-(la + ha));
        S1 += __expf(-(lb + hb));
    }

    red[q][jj][0] = S0;
    red[q][jj][1] = S1;
    __syncthreads();

    if (q == 0) {
        float t0 = red[0][jj][0] + red[1][jj][0] + red[2][jj][0] + red[3][jj][0];
        float t1 = red[0][jj][1] + red[1][jj][1] + red[2][jj][1] + red[3][jj][1];
        out[j0 * OUT_F + o]       = w[j0]     * (t0 - 1.0f);
        out[(j0 + 1) * OUT_F + o] = w[j0 + 1] * (t1 - 1.0f);
    }
}

// ---------------------------------------------------------------------------
extern "C" void kernel_launch(void* const* d_in, const int* in_sizes, int n_in,
                              void* d_out, int out_size)
{
    const float* x = (const float*)d_in[0];   // [512, 512]
    const float* w = (const float*)d_in[1];   // [1, 512]
    const float* T = (const float*)d_in[2];   // [512, 64, 16]
    float* out = (float*)d_out;               // [512, 64]

    (void)in_sizes; (void)n_in; (void)out_size;

    mbd_gemm_kernel<<<dim3(NF / TN, B_SZ / TM), 256>>>(x, T);
    mbd_pairwise_kernel<<<dim3(OUT_F, 8), 128>>>(w, out);
}

// round 4
// speedup vs baseline: 1.0702x; 1.0702x over previous
#include <cuda_runtime.h>
#include <cuda_bf16.h>

// Problem constants
#define B_SZ   512
#define IN_F   512
#define OUT_F  64
#define KD     16
#define NF     (OUT_F * KD)   // 1024

typedef unsigned long long u64;

// Scratch: M laid out [o][b][k]  (2 MB), S accumulator laid out [j][o] (128 KB)
__device__ float g_M[OUT_F * B_SZ * KD];
__device__ float g_S[B_SZ * OUT_F];

// ---- packed f32x2 helpers (sm_103a) ---------------------------------------
__device__ __forceinline__ u64 fadd2(u64 a, u64 b) {
    u64 r; asm("add.rn.f32x2 %0, %1, %2;" : "=l"(r) : "l"(a), "l"(b)); return r;
}
__device__ __forceinline__ u64 ffma2(u64 a, u64 b, u64 c) {
    u64 r; asm("fma.rn.f32x2 %0, %1, %2, %3;" : "=l"(r) : "l"(a), "l"(b), "l"(c)); return r;
}
__device__ __forceinline__ u64 fabs2(u64 a) {
    return a & 0x7FFFFFFF7FFFFFFFULL;            // sign clear -> alu pipe
}
__device__ __forceinline__ u64 pack2(float lo, float hi) {
    u64 r; asm("mov.b64 %0, {%1, %2};" : "=l"(r) : "f"(lo), "f"(hi)); return r;
}
__device__ __forceinline__ void unpack2(u64 v, float& lo, float& hi) {
    asm("mov.b64 {%0, %1}, %2;" : "=f"(lo), "=f"(hi) : "l"(v));
}

// ---------------------------------------------------------------------------
// Kernel A: M = x[512,512] @ T[512,1024] -> g_M[o][b][k];  also zeroes g_S.
// TM=32, TN=64, TK=16, 128 threads, 4x4 microtile, A duplicated as (a,a):
// inner loop = 4 LDS.64 + 1 LDS.128 + 8 FFMA2  (fma-bound).
// Grid (16,16) = 256 blocks.
// ---------------------------------------------------------------------------
#define TM 32
#define TN 64
#define TK 16

__global__ __launch_bounds__(128) void mbd_gemm_kernel(
    const float* __restrict__ x, const float* __restrict__ T)
{
    __shared__ float2 xsd[TM][TK];     // duplicated A (a,a): 4 KB
    __shared__ float  Ts[TK][TN];      // 4 KB

    const int tid = threadIdx.x;

    // Zero g_S (256 blocks x 128 threads = 32768 = B_SZ*OUT_F)
    {
        int bid = blockIdx.y * gridDim.x + blockIdx.x;
        g_S[bid * 128 + tid] = 0.0f;
    }

    const int tx = tid & 15;           // 16 -> 4 cols each
    const int ty = tid >> 4;           // 8  -> 4 rows each
    const int m0 = blockIdx.y * TM;
    const int n0 = blockIdx.x * TN;
    const int r = ty * 4;
    const int c = tx * 4;

    u64 acc[4][2];
#pragma unroll
    for (int i = 0; i < 4; i++) { acc[i][0] = 0ULL; acc[i][1] = 0ULL; }

    for (int k0 = 0; k0 < IN_F; k0 += TK) {
        // A tile 32x16 = 512 floats: one float4 per thread, stored duplicated
        {
            int idx = tid * 4;
            int m = idx >> 4;
            int k = idx & 15;
            float4 v = *(const float4*)&x[(m0 + m) * IN_F + k0 + k];
            xsd[m][k + 0] = make_float2(v.x, v.x);
            xsd[m][k + 1] = make_float2(v.y, v.y);
            xsd[m][k + 2] = make_float2(v.z, v.z);
            xsd[m][k + 3] = make_float2(v.w, v.w);
        }
        // B tile 16x64 = 1024 floats: two float4 per thread
#pragma unroll
        for (int t = 0; t < 2; t++) {
            int idx = tid * 4 + t * 512;
            int k = idx >> 6;
            int n = idx & 63;
            float4 v = *(const float4*)&T[(k0 + k) * NF + n0 + n];
            *(float4*)&Ts[k][n] = v;
        }
        __syncthreads();

#pragma unroll
        for (int kk = 0; kk < TK; kk++) {
            u64 a0 = *(const u64*)&xsd[r + 0][kk];
            u64 a1 = *(const u64*)&xsd[r + 1][kk];
            u64 a2 = *(const u64*)&xsd[r + 2][kk];
            u64 a3 = *(const u64*)&xsd[r + 3][kk];
            ulonglong2 bb = *(const ulonglong2*)&Ts[kk][c];
            acc[0][0] = ffma2(a0, bb.x, acc[0][0]); acc[0][1] = ffma2(a0, bb.y, acc[0][1]);
            acc[1][0] = ffma2(a1, bb.x, acc[1][0]); acc[1][1] = ffma2(a1, bb.y, acc[1][1]);
            acc[2][0] = ffma2(a2, bb.x, acc[2][0]); acc[2][1] = ffma2(a2, bb.y, acc[2][1]);
            acc[3][0] = ffma2(a3, bb.x, acc[3][0]); acc[3][1] = ffma2(a3, bb.y, acc[3][1]);
        }
        __syncthreads();
    }

    // Epilogue: g_M[o][b][k]. c multiple of 4 -> 4 cols inside one o.
    const int of = n0 + c;
    const int o  = of >> 4;
    const int k  = of & 15;
#pragma unroll
    for (int ii = 0; ii < 4; ii++) {
        int b = m0 + r + ii;
        ulonglong2 v; v.x = acc[ii][0]; v.y = acc[ii][1];
        *(ulonglong2*)&g_M[(o * B_SZ + b) * KD + k] = v;
    }
}

// ---------------------------------------------------------------------------
// Kernel B: fine-grained pairwise tiles.
// grid (64 o, 4 j-chunk, 4 i-quarter), 128 threads; thread = one j, 128 i's.
// Stages its 128 j-rows + 128 i-rows (16 KB). Partial S -> REDG into g_S[j][o].
// ---------------------------------------------------------------------------
__global__ __launch_bounds__(128) void mbd_pairwise_kernel(void)
{
    __shared__ float sJ[128 * KD];             // 8 KB
    __shared__ float sI[128 * KD];             // 8 KB

    const int o   = blockIdx.x;
    const int jc  = blockIdx.y;                // j-chunk 0..3 (128 j's)
    const int q   = blockIdx.z;                // i-quarter 0..3 (128 i's)
    const int tid = threadIdx.x;
    const int j   = jc * 128 + tid;

    // Stage j-rows and i-rows (each 2048 floats = 512 float4)
    {
        const float4* baseJ = (const float4*)(g_M + (o * B_SZ + jc * 128) * KD);
        const float4* baseI = (const float4*)(g_M + (o * B_SZ + q  * 128) * KD);
        float4* dJ = (float4*)sJ;
        float4* dI = (float4*)sI;
#pragma unroll
        for (int t = 0; t < 4; t++) {
            dJ[tid + t * 128] = baseJ[tid + t * 128];
            dI[tid + t * 128] = baseI[tid + t * 128];
        }
    }
    __syncthreads();

    // Pre-negated packed row j
    u64 mjn[8];
#pragma unroll
    for (int p = 0; p < 8; p++)
        mjn[p] = pack2(-sJ[tid * KD + 2 * p], -sJ[tid * KD + 2 * p + 1]);

    const ulonglong2* s2 = (const ulonglong2*)sI;
    float S = 0.f;

#pragma unroll 2
    for (int i = 0; i < 128; i++) {
        ulonglong2 v0 = s2[i * 4 + 0];         // warp-uniform -> LDS broadcast
        ulonglong2 v1 = s2[i * 4 + 1];
        ulonglong2 v2 = s2[i * 4 + 2];
        ulonglong2 v3 = s2[i * 4 + 3];
        u64 a0 = fabs2(fadd2(v0.x, mjn[0]));
        u64 a1 = fabs2(fadd2(v0.y, mjn[1]));
        u64 a2 = fabs2(fadd2(v1.x, mjn[2]));
        u64 a3 = fabs2(fadd2(v1.y, mjn[3]));
        u64 a4 = fabs2(fadd2(v2.x, mjn[4]));
        u64 a5 = fabs2(fadd2(v2.y, mjn[5]));
        u64 a6 = fabs2(fadd2(v3.x, mjn[6]));
        u64 a7 = fabs2(fadd2(v3.y, mjn[7]));
        u64 t = fadd2(fadd2(fadd2(a0, a1), fadd2(a2, a3)),
                      fadd2(fadd2(a4, a5), fadd2(a6, a7)));
        float lo, hi; unpack2(t, lo, hi);
        S += __expf(-(lo + hi));
    }

    atomicAdd(&g_S[j * OUT_F + o], S);         // REDG, 131K total adds
}

// ---------------------------------------------------------------------------
// Kernel C: out[j,o] = w[j] * (g_S[j,o] - 1)   (coalesced both sides)
// ---------------------------------------------------------------------------
__global__ __launch_bounds__(256) void mbd_finalize_kernel(
    const float* __restrict__ w, float* __restrict__ out)
{
    int idx = blockIdx.x * 256 + threadIdx.x;  // 0 .. 32767
    int j = idx >> 6;
    out[idx] = w[j] * (g_S[idx] - 1.0f);
}

// ---------------------------------------------------------------------------
extern "C" void kernel_launch(void* const* d_in, const int* in_sizes, int n_in,
                              void* d_out, int out_size)
{
    const float* x = (const float*)d_in[0];   // [512, 512]
    const float* w = (const float*)d_in[1];   // [1, 512]
    const float* T = (const float*)d_in[2];   // [512, 64, 16]
    float* out = (float*)d_out;               // [512, 64]

    (void)in_sizes; (void)n_in; (void)out_size;

    mbd_gemm_kernel<<<dim3(NF / TN, B_SZ / TM), 128>>>(x, T);
    mbd_pairwise_kernel<<<dim3(OUT_F, 4, 4), 128>>>();
    mbd_finalize_kernel<<<(B_SZ * OUT_F) / 256, 256>>>(w, out);
}

// round 5
// speedup vs baseline: 1.1280x; 1.0540x over previous
#include <cuda_runtime.h>
#include <cuda_bf16.h>

// Problem constants
#define B_SZ   512
#define IN_F   512
#define OUT_F  64
#define KD     16
#define NF     (OUT_F * KD)   // 1024
#define KS     4              // k-splits in GEMM

typedef unsigned long long u64;

// Scratch: 4 partial M buffers laid out [o][b][k] (4 x 2 MB),
// S accumulator laid out [j][o] (128 KB)
__device__ float g_Mp[KS][OUT_F * B_SZ * KD];
__device__ float g_S[B_SZ * OUT_F];

// ---- packed f32x2 helpers (sm_103a) ---------------------------------------
__device__ __forceinline__ u64 fadd2(u64 a, u64 b) {
    u64 r; asm("add.rn.f32x2 %0, %1, %2;" : "=l"(r) : "l"(a), "l"(b)); return r;
}
__device__ __forceinline__ u64 ffma2(u64 a, u64 b, u64 c) {
    u64 r; asm("fma.rn.f32x2 %0, %1, %2, %3;" : "=l"(r) : "l"(a), "l"(b), "l"(c)); return r;
}
__device__ __forceinline__ u64 fabs2(u64 a) {
    return a & 0x7FFFFFFF7FFFFFFFULL;            // sign clear -> alu pipe
}
__device__ __forceinline__ u64 pack2(float lo, float hi) {
    u64 r; asm("mov.b64 %0, {%1, %2};" : "=l"(r) : "f"(lo), "f"(hi)); return r;
}
__device__ __forceinline__ void unpack2(u64 v, float& lo, float& hi) {
    asm("mov.b64 {%0, %1}, %2;" : "=f"(lo), "=f"(hi) : "l"(v));
}

// ---------------------------------------------------------------------------
// Kernel A: k-split GEMM.  Block (nt, mt, ks) computes the 64x64 tile
// (rows mt*64, cols nt*64) of  x @ T  restricted to K in [ks*128, ks*128+128),
// writing the partial to g_Mp[ks] in [o][b][k] layout.
// 256 threads, TK=16, 4x4 microtile, FFMA2 with A pre-duplicated as (a,a).
// Grid (16, 8, 4) = 512 blocks  ->  ~28 warps/SM.
// ---------------------------------------------------------------------------
#define TM 64
#define TN 64
#define TK 16
#define KC (IN_F / KS)        // 128

__global__ __launch_bounds__(256) void mbd_gemm_kernel(
    const float* __restrict__ x, const float* __restrict__ T)
{
    __shared__ float2 xsd[TM][TK];     // duplicated A (a,a): 8 KB
    __shared__ float  Ts[TK][TN];      // 4 KB

    const int tid = threadIdx.x;
    const int nt  = blockIdx.x;
    const int mt  = blockIdx.y;
    const int ks  = blockIdx.z;

    // g_S zeroing, done once by the ks==0 plane (128 blocks x 256 = 32768)
    if (ks == 0) {
        int id = mt * 16 + nt;
        g_S[id * 256 + tid] = 0.0f;
    }

    const int tx = tid & 15;           // 4 cols each
    const int ty = tid >> 4;           // 4 rows each
    const int m0 = mt * TM;
    const int n0 = nt * TN;
    const int kb = ks * KC;
    const int r = ty * 4;
    const int c = tx * 4;

    u64 acc[4][2];
#pragma unroll
    for (int i = 0; i < 4; i++) { acc[i][0] = 0ULL; acc[i][1] = 0ULL; }

    for (int k0 = 0; k0 < KC; k0 += TK) {
        // A tile 64x16 = 1024 floats: one float4/thread, stored duplicated
        {
            int idx = tid * 4;
            int m = idx >> 4;
            int k = idx & 15;
            float4 v = *(const float4*)&x[(m0 + m) * IN_F + kb + k0 + k];
            xsd[m][k + 0] = make_float2(v.x, v.x);
            xsd[m][k + 1] = make_float2(v.y, v.y);
            xsd[m][k + 2] = make_float2(v.z, v.z);
            xsd[m][k + 3] = make_float2(v.w, v.w);
        }
        // B tile 16x64 = 1024 floats: one float4/thread
        {
            int idx = tid * 4;
            int k = idx >> 6;
            int n = idx & 63;
            float4 v = *(const float4*)&T[(kb + k0 + k) * NF + n0 + n];
            *(float4*)&Ts[k][n] = v;
        }
        __syncthreads();

#pragma unroll
        for (int kk = 0; kk < TK; kk++) {
            u64 a0 = *(const u64*)&xsd[r + 0][kk];
            u64 a1 = *(const u64*)&xsd[r + 1][kk];
            u64 a2 = *(const u64*)&xsd[r + 2][kk];
            u64 a3 = *(const u64*)&xsd[r + 3][kk];
            ulonglong2 bb = *(const ulonglong2*)&Ts[kk][c];
            acc[0][0] = ffma2(a0, bb.x, acc[0][0]); acc[0][1] = ffma2(a0, bb.y, acc[0][1]);
            acc[1][0] = ffma2(a1, bb.x, acc[1][0]); acc[1][1] = ffma2(a1, bb.y, acc[1][1]);
            acc[2][0] = ffma2(a2, bb.x, acc[2][0]); acc[2][1] = ffma2(a2, bb.y, acc[2][1]);
            acc[3][0] = ffma2(a3, bb.x, acc[3][0]); acc[3][1] = ffma2(a3, bb.y, acc[3][1]);
        }
        __syncthreads();
    }

    // Epilogue: partial -> g_Mp[ks][o][b][k]. c multiple of 4 -> one o.
    const int of = n0 + c;
    const int o  = of >> 4;
    const int k  = of & 15;
    float* dst = g_Mp[ks];
#pragma unroll
    for (int ii = 0; ii < 4; ii++) {
        int b = m0 + r + ii;
        ulonglong2 v; v.x = acc[ii][0]; v.y = acc[ii][1];
        *(ulonglong2*)&dst[(o * B_SZ + b) * KD + k] = v;
    }
}

// ---------------------------------------------------------------------------
// Kernel B: fine-grained pairwise tiles.
// grid (64 o, 4 j-chunk, 4 i-quarter), 128 threads; thread = one j, 128 i's.
// Staging sums the 4 GEMM partials. Partial S -> REDG into g_S[j][o].
// ---------------------------------------------------------------------------
__global__ __launch_bounds__(128) void mbd_pairwise_kernel(void)
{
    __shared__ float sJ[128 * KD];             // 8 KB
    __shared__ float sI[128 * KD];             // 8 KB

    const int o   = blockIdx.x;
    const int jc  = blockIdx.y;                // j-chunk (128 j's)
    const int q   = blockIdx.z;                // i-quarter (128 i's)
    const int tid = threadIdx.x;
    const int j   = jc * 128 + tid;

    // Stage j-rows and i-rows, summing the 4 k-split partials
    {
        const int offJ = (o * B_SZ + jc * 128) * KD / 4;   // float4 units
        const int offI = (o * B_SZ + q  * 128) * KD / 4;
        float4* dJ = (float4*)sJ;
        float4* dI = (float4*)sI;
#pragma unroll
        for (int t = 0; t < 4; t++) {
            int e = tid + t * 128;
            float4 aJ = ((const float4*)g_Mp[0])[offJ + e];
            float4 bJ = ((const float4*)g_Mp[1])[offJ + e];
            float4 cJ = ((const float4*)g_Mp[2])[offJ + e];
            float4 eJ = ((const float4*)g_Mp[3])[offJ + e];
            dJ[e] = make_float4((aJ.x + bJ.x) + (cJ.x + eJ.x),
                                (aJ.y + bJ.y) + (cJ.y + eJ.y),
                                (aJ.z + bJ.z) + (cJ.z + eJ.z),
                                (aJ.w + bJ.w) + (cJ.w + eJ.w));
            float4 aI = ((const float4*)g_Mp[0])[offI + e];
            float4 bI = ((const float4*)g_Mp[1])[offI + e];
            float4 cI = ((const float4*)g_Mp[2])[offI + e];
            float4 eI = ((const float4*)g_Mp[3])[offI + e];
            dI[e] = make_float4((aI.x + bI.x) + (cI.x + eI.x),
                                (aI.y + bI.y) + (cI.y + eI.y),
                                (aI.z + bI.z) + (cI.z + eI.z),
                                (aI.w + bI.w) + (cI.w + eI.w));
        }
    }
    __syncthreads();

    // Pre-negated packed row j
    u64 mjn[8];
#pragma unroll
    for (int p = 0; p < 8; p++)
        mjn[p] = pack2(-sJ[tid * KD + 2 * p], -sJ[tid * KD + 2 * p + 1]);

    const ulonglong2* s2 = (const ulonglong2*)sI;
    float S = 0.f;

#pragma unroll 2
    for (int i = 0; i < 128; i++) {
        ulonglong2 v0 = s2[i * 4 + 0];         // warp-uniform -> LDS broadcast
        ulonglong2 v1 = s2[i * 4 + 1];
        ulonglong2 v2 = s2[i * 4 + 2];
        ulonglong2 v3 = s2[i * 4 + 3];
        u64 a0 = fabs2(fadd2(v0.x, mjn[0]));
        u64 a1 = fabs2(fadd2(v0.y, mjn[1]));
        u64 a2 = fabs2(fadd2(v1.x, mjn[2]));
        u64 a3 = fabs2(fadd2(v1.y, mjn[3]));
        u64 a4 = fabs2(fadd2(v2.x, mjn[4]));
        u64 a5 = fabs2(fadd2(v2.y, mjn[5]));
        u64 a6 = fabs2(fadd2(v3.x, mjn[6]));
        u64 a7 = fabs2(fadd2(v3.y, mjn[7]));
        u64 t = fadd2(fadd2(fadd2(a0, a1), fadd2(a2, a3)),
                      fadd2(fadd2(a4, a5), fadd2(a6, a7)));
        float lo, hi; unpack2(t, lo, hi);
        S += __expf(-(lo + hi));
    }

    atomicAdd(&g_S[j * OUT_F + o], S);         // REDG, 131K total adds
}

// ---------------------------------------------------------------------------
// Kernel C: out[j,o] = w[j] * (g_S[j,o] - 1)   (coalesced both sides)
// ---------------------------------------------------------------------------
__global__ __launch_bounds__(256) void mbd_finalize_kernel(
    const float* __restrict__ w, float* __restrict__ out)
{
    int idx = blockIdx.x * 256 + threadIdx.x;  // 0 .. 32767
    int j = idx >> 6;
    out[idx] = w[j] * (g_S[idx] - 1.0f);
}

// ---------------------------------------------------------------------------
extern "C" void kernel_launch(void* const* d_in, const int* in_sizes, int n_in,
                              void* d_out, int out_size)
{
    const float* x = (const float*)d_in[0];   // [512, 512]
    const float* w = (const float*)d_in[1];   // [1, 512]
    const float* T = (const float*)d_in[2];   // [512, 64, 16]
    float* out = (float*)d_out;               // [512, 64]

    (void)in_sizes; (void)n_in; (void)out_size;

    mbd_gemm_kernel<<<dim3(NF / TN, B_SZ / TM, KS), 256>>>(x, T);
    mbd_pairwise_kernel<<<dim3(OUT_F, 4, 4), 128>>>();
    mbd_finalize_kernel<<<(B_SZ * OUT_F) / 256, 256>>>(w, out);
}